// round 10
// baseline (speedup 1.0000x reference)
#include <cuda_runtime.h>
#include <math.h>

// EmbeddingToExpression: per-region MLP 16 -> 5 (exact-erf GELU) -> 1
//   R=1024, C=8192, DIN=16, E=5, NREG=2048. out[c,r] f32.
//
// R10 = R9 (cp.async ring, warp-per-region, region-fast grid, hoisted
// swizzle, folded GELU consts, branchless A&S erf) +
//  - CPB 512 (PASSES=16): halves per-block prologue/epilogue overhead,
//    the load-dead windows that cap DRAM at 76%.
//  - erf poly 5-term -> 3-term (A&S 7.1.25, abs err 2.5e-5; output err
//    ~1e-5, 100x under the 1e-3 gate). -10 instr/cell.
//  - DEPTH 4 (SMEM 32K ring + 8K s_out = 41 KB).

#define RR      1024
#define CC      8192
#define DIN     16
#define EE      5
#define CPB     512          // cells per block
#define RPB     4            // regions per block (one warp each)
#define PASSES  16           // CPB / 32
#define DEPTH   4            // pipeline ring depth
#define STAGE_B 2048         // 32 cells * 64 B per warp-pass

__device__ __forceinline__ unsigned sw128(unsigned o) {
    return o ^ ((o >> 3) & 0x70);
}
__device__ __forceinline__ void cp16(unsigned dst, const void* src) {
    asm volatile("cp.async.cg.shared.global [%0], [%1], 16;\n"
                 :: "r"(dst), "l"(src));
}
__device__ __forceinline__ void cp_commit() {
    asm volatile("cp.async.commit_group;\n" ::: "memory");
}
__device__ __forceinline__ void cp_wait3() {
    asm volatile("cp.async.wait_group 3;\n" ::: "memory");
}

// 1 + erf(x), branchless. Abramowitz-Stegun 7.1.25, |abs err| <= 2.5e-5.
// Tails exact via exp underflow: x<<0 -> 0, x>>0 -> 2.
__device__ __forceinline__ float erf1p(float x) {
    const float p  = 0.47047f;
    const float a1 = 0.3480242f, a2 = -0.0958798f, a3 = 0.7478556f;
    float ax = fabsf(x);
    float t  = __fdividef(1.0f, fmaf(p, ax, 1.0f));   // MUFU.RCP path
    float r  = fmaf(a3, t, a2);
    r = fmaf(r, t, a1);
    r = r * t;
    float u = r * __expf(-x * x);                     // MUFU.EX2 path
    return 1.0f + copysignf(1.0f - u, x);
}

__global__ __launch_bounds__(128, 4)
void e2e_kernel(const float* __restrict__ emb,
                const void*  __restrict__ oi,     // int32 or int64, detected
                const float* __restrict__ W1,     // [NREG, DIN, E]
                const float* __restrict__ b1,     // [NREG, E]
                const float* __restrict__ Wf,     // [NREG, E, 1]
                float* __restrict__ out)          // [C, R]
{
    __shared__ __align__(1024) char s_stage[RPB * DEPTH * STAGE_B]; // 32 KB
    __shared__ float s_out[RPB * CPB];                              // 8 KB
    __shared__ int   s_is64;

    // Detect regions_oi width (values < 2048 => int64 high words are 0).
    if (threadIdx.x == 0) {
        const int* w = (const int*)oi;
        int all0 = 1;
        #pragma unroll
        for (int k = 0; k < 32; k++) all0 &= (w[2 * k + 1] == 0);
        s_is64 = all0;
    }
    __syncthreads();

    const int warp = threadIdx.x >> 5;
    const int lane = threadIdx.x & 31;
    const int r    = blockIdx.x * RPB + warp;   // region group = FAST grid dim
    const int c0   = blockIdx.y * CPB;

    int reg;
    if (s_is64) reg = (int)((const long long*)oi)[r];
    else        reg = ((const int*)oi)[r];

    // ---- hoisted swizzled offsets + pipeline bases ----
    const char* gsrc = (const char*)(emb + ((size_t)r * CC + c0) * DIN);
    char*       wbuf = s_stage + warp * (DEPTH * STAGE_B);
    const unsigned sbase = (unsigned)__cvta_generic_to_shared(wbuf);
    unsigned po[4], co[4];
    #pragma unroll
    for (int k = 0; k < 4; k++) {
        po[k] = sw128(k * 512 + lane * 16);     // producer dst offsets
        co[k] = sw128(lane * 64 + k * 16);      // consumer src offsets
    }
    const unsigned goff = lane * 16;

    // ---- start DRAM traffic first: prologue passes 0..2 as groups 0..2 ----
    #pragma unroll
    for (int g = 0; g < DEPTH - 1; g++) {
        const unsigned slot = sbase + (g % DEPTH) * STAGE_B;
        const char* s = gsrc + g * STAGE_B + goff;
        cp16(slot + po[0], s);
        cp16(slot + po[1], s + 512);
        cp16(slot + po[2], s + 1024);
        cp16(slot + po[3], s + 1536);
        cp_commit();
    }

    // ---- weights, prescaled by 1/sqrt(2) so h' = h/sqrt(2) ----
    const float KI = 0.70710678118654752f;      // 1/sqrt(2)
    const float KQ = 0.70710678118654752f;      // 0.5/KI
    float w[DIN * EE];
    {
        const float4* wp = (const float4*)(W1 + (size_t)reg * (DIN * EE));
        #pragma unroll
        for (int q = 0; q < (DIN * EE) / 4; q++) {
            float4 v = wp[q];
            w[4 * q + 0] = v.x * KI; w[4 * q + 1] = v.y * KI;
            w[4 * q + 2] = v.z * KI; w[4 * q + 3] = v.w * KI;
        }
    }
    float bb[EE], wq[EE];
    #pragma unroll
    for (int e = 0; e < EE; e++) {
        bb[e] = b1[reg * EE + e] * KI;
        wq[e] = Wf[reg * EE + e] * KQ;          // 0.5/KI * wf
    }

    #pragma unroll
    for (int p = 0; p < PASSES; p++) {
        const int g = p + DEPTH - 1;
        if (g < PASSES) {
            const unsigned slot = sbase + (g % DEPTH) * STAGE_B;
            const char* s = gsrc + g * STAGE_B + goff;
            cp16(slot + po[0], s);
            cp16(slot + po[1], s + 512);
            cp16(slot + po[2], s + 1024);
            cp16(slot + po[3], s + 1536);
        }
        cp_commit();
        cp_wait3();   // all but newest 3 groups done => pass p landed

        // ---- compute pass p from SMEM (conflict-free LDS.128) ----
        const char* xb = wbuf + (p % DEPTH) * STAGE_B;
        float4 v0 = *(const float4*)(xb + co[0]);
        float4 v1 = *(const float4*)(xb + co[1]);
        float4 v2 = *(const float4*)(xb + co[2]);
        float4 v3 = *(const float4*)(xb + co[3]);

        float h0 = bb[0], h1 = bb[1], h2 = bb[2], h3 = bb[3], h4 = bb[4];
        #define ACC(V, I) \
            h0 = fmaf((V), w[(I) * EE + 0], h0); \
            h1 = fmaf((V), w[(I) * EE + 1], h1); \
            h2 = fmaf((V), w[(I) * EE + 2], h2); \
            h3 = fmaf((V), w[(I) * EE + 3], h3); \
            h4 = fmaf((V), w[(I) * EE + 4], h4);
        ACC(v0.x, 0)  ACC(v0.y, 1)  ACC(v0.z, 2)  ACC(v0.w, 3)
        ACC(v1.x, 4)  ACC(v1.y, 5)  ACC(v1.z, 6)  ACC(v1.w, 7)
        ACC(v2.x, 8)  ACC(v2.y, 9)  ACC(v2.z,10)  ACC(v2.w,11)
        ACC(v3.x,12)  ACC(v3.y,13)  ACC(v3.z,14)  ACC(v3.w,15)
        #undef ACC

        // gelu(h)*wf == h' * (1 + erf(h')) * (0.5/KI)*wf,  h' = h/sqrt(2)
        float q0 = erf1p(h0);
        float q1 = erf1p(h1);
        float q2 = erf1p(h2);
        float q3 = erf1p(h3);
        float q4 = erf1p(h4);
        float acc = (h0 * wq[0]) * q0;
        acc = fmaf(h1 * wq[1], q1, acc);
        acc = fmaf(h2 * wq[2], q2, acc);
        acc = fmaf(h3 * wq[3], q3, acc);
        acc = fmaf(h4 * wq[4], q4, acc);

        s_out[warp * CPB + (p * 32 + lane)] = acc;
    }
    __syncthreads();

    // ---- transposed write: 16B per thread-cell; adjacent blockIdx.x
    //      supplies the neighboring half-sector -> L2 write-merge.
    #pragma unroll
    for (int cc = 0; cc < CPB; cc += 128) {
        const int c = cc + threadIdx.x;
        float4 o;
        o.x = s_out[0 * CPB + c];
        o.y = s_out[1 * CPB + c];
        o.z = s_out[2 * CPB + c];
        o.w = s_out[3 * CPB + c];
        float* op = out + (size_t)(c0 + c) * RR + (size_t)blockIdx.x * RPB;
        *(float4*)op = o;
    }
}

extern "C" void kernel_launch(void* const* d_in, const int* in_sizes, int n_in,
                              void* d_out, int out_size)
{
    const float* emb = (const float*)d_in[0];   // [R, C, DIN] f32
    const void*  oi  = d_in[1];                 // [R] int32/int64
    const float* W1  = (const float*)d_in[2];   // [NREG, DIN, E]
    const float* b1  = (const float*)d_in[3];   // [NREG, E]
    const float* Wf  = (const float*)d_in[4];   // [NREG, E, 1]
    float* out = (float*)d_out;                 // [C, R]

    dim3 grid(RR / RPB, CC / CPB);              // (256, 16) region-group fast
    e2e_kernel<<<grid, 128>>>(emb, oi, W1, b1, Wf, out);
}

// round 11
// speedup vs baseline: 1.0229x; 1.0229x over previous
#include <cuda_runtime.h>
#include <math.h>

// EmbeddingToExpression: per-region MLP 16 -> 5 (exact-erf GELU) -> 1
//   R=1024, C=8192, DIN=16, E=5, NREG=2048. out[c,r] f32.
//
// R11 = R9 structure EXACTLY (CPB=256, DEPTH=5 ring, warp-per-region,
// region-fast grid, hoisted swizzle, folded GELU consts) with ONE change
// kept from R10: 3-term A&S 7.1.25 erf (abs err 2.5e-5 -> output ~1e-5,
// 100x under gate). R10's CPB=512 reverted: longer blocks increased
// cross-CTA skew and LOWERED DRAM util (76.0 -> 72.3%).

#define RR      1024
#define CC      8192
#define DIN     16
#define EE      5
#define CPB     256          // cells per block
#define RPB     4            // regions per block (one warp each)
#define PASSES  8            // CPB / 32
#define DEPTH   5            // pipeline ring depth
#define STAGE_B 2048         // 32 cells * 64 B per warp-pass

__device__ __forceinline__ unsigned sw128(unsigned o) {
    return o ^ ((o >> 3) & 0x70);
}
__device__ __forceinline__ void cp16(unsigned dst, const void* src) {
    asm volatile("cp.async.cg.shared.global [%0], [%1], 16;\n"
                 :: "r"(dst), "l"(src));
}
__device__ __forceinline__ void cp_commit() {
    asm volatile("cp.async.commit_group;\n" ::: "memory");
}
__device__ __forceinline__ void cp_wait4() {
    asm volatile("cp.async.wait_group 4;\n" ::: "memory");
}

// 1 + erf(x), branchless. Abramowitz-Stegun 7.1.25, |abs err| <= 2.5e-5.
// Tails exact via exp underflow: x<<0 -> 0, x>>0 -> 2.
__device__ __forceinline__ float erf1p(float x) {
    const float p  = 0.47047f;
    const float a1 = 0.3480242f, a2 = -0.0958798f, a3 = 0.7478556f;
    float ax = fabsf(x);
    float t  = __fdividef(1.0f, fmaf(p, ax, 1.0f));   // MUFU.RCP path
    float r  = fmaf(a3, t, a2);
    r = fmaf(r, t, a1);
    r = r * t;
    float u = r * __expf(-x * x);                     // MUFU.EX2 path
    return 1.0f + copysignf(1.0f - u, x);
}

__global__ __launch_bounds__(128, 4)
void e2e_kernel(const float* __restrict__ emb,
                const void*  __restrict__ oi,     // int32 or int64, detected
                const float* __restrict__ W1,     // [NREG, DIN, E]
                const float* __restrict__ b1,     // [NREG, E]
                const float* __restrict__ Wf,     // [NREG, E, 1]
                float* __restrict__ out)          // [C, R]
{
    __shared__ __align__(1024) char s_stage[RPB * DEPTH * STAGE_B]; // 40 KB
    __shared__ float s_out[RPB * CPB];                              // 4 KB
    __shared__ int   s_is64;

    // Detect regions_oi width (values < 2048 => int64 high words are 0).
    if (threadIdx.x == 0) {
        const int* w = (const int*)oi;
        int all0 = 1;
        #pragma unroll
        for (int k = 0; k < 32; k++) all0 &= (w[2 * k + 1] == 0);
        s_is64 = all0;
    }
    __syncthreads();

    const int warp = threadIdx.x >> 5;
    const int lane = threadIdx.x & 31;
    const int r    = blockIdx.x * RPB + warp;   // region group = FAST grid dim
    const int c0   = blockIdx.y * CPB;

    int reg;
    if (s_is64) reg = (int)((const long long*)oi)[r];
    else        reg = ((const int*)oi)[r];

    // ---- hoisted swizzled offsets + pipeline bases ----
    const char* gsrc = (const char*)(emb + ((size_t)r * CC + c0) * DIN);
    char*       wbuf = s_stage + warp * (DEPTH * STAGE_B);
    const unsigned sbase = (unsigned)__cvta_generic_to_shared(wbuf);
    unsigned po[4], co[4];
    #pragma unroll
    for (int k = 0; k < 4; k++) {
        po[k] = sw128(k * 512 + lane * 16);     // producer dst offsets
        co[k] = sw128(lane * 64 + k * 16);      // consumer src offsets
    }
    const unsigned goff = lane * 16;

    // ---- start DRAM traffic first: prologue passes 0..3 as groups 0..3 ----
    #pragma unroll
    for (int g = 0; g < DEPTH - 1; g++) {
        const unsigned slot = sbase + (g % DEPTH) * STAGE_B;
        const char* s = gsrc + g * STAGE_B + goff;
        cp16(slot + po[0], s);
        cp16(slot + po[1], s + 512);
        cp16(slot + po[2], s + 1024);
        cp16(slot + po[3], s + 1536);
        cp_commit();
    }

    // ---- weights, prescaled by 1/sqrt(2) so h' = h/sqrt(2) ----
    const float KI = 0.70710678118654752f;      // 1/sqrt(2)
    const float KQ = 0.70710678118654752f;      // 0.5/KI
    float w[DIN * EE];
    {
        const float4* wp = (const float4*)(W1 + (size_t)reg * (DIN * EE));
        #pragma unroll
        for (int q = 0; q < (DIN * EE) / 4; q++) {
            float4 v = wp[q];
            w[4 * q + 0] = v.x * KI; w[4 * q + 1] = v.y * KI;
            w[4 * q + 2] = v.z * KI; w[4 * q + 3] = v.w * KI;
        }
    }
    float bb[EE], wq[EE];
    #pragma unroll
    for (int e = 0; e < EE; e++) {
        bb[e] = b1[reg * EE + e] * KI;
        wq[e] = Wf[reg * EE + e] * KQ;          // 0.5/KI * wf
    }

    #pragma unroll
    for (int p = 0; p < PASSES; p++) {
        const int g = p + DEPTH - 1;
        if (g < PASSES) {
            const unsigned slot = sbase + (g % DEPTH) * STAGE_B;
            const char* s = gsrc + g * STAGE_B + goff;
            cp16(slot + po[0], s);
            cp16(slot + po[1], s + 512);
            cp16(slot + po[2], s + 1024);
            cp16(slot + po[3], s + 1536);
        }
        cp_commit();
        cp_wait4();   // all but newest 4 groups done => pass p landed

        // ---- compute pass p from SMEM (conflict-free LDS.128) ----
        const char* xb = wbuf + (p % DEPTH) * STAGE_B;
        float4 v0 = *(const float4*)(xb + co[0]);
        float4 v1 = *(const float4*)(xb + co[1]);
        float4 v2 = *(const float4*)(xb + co[2]);
        float4 v3 = *(const float4*)(xb + co[3]);

        float h0 = bb[0], h1 = bb[1], h2 = bb[2], h3 = bb[3], h4 = bb[4];
        #define ACC(V, I) \
            h0 = fmaf((V), w[(I) * EE + 0], h0); \
            h1 = fmaf((V), w[(I) * EE + 1], h1); \
            h2 = fmaf((V), w[(I) * EE + 2], h2); \
            h3 = fmaf((V), w[(I) * EE + 3], h3); \
            h4 = fmaf((V), w[(I) * EE + 4], h4);
        ACC(v0.x, 0)  ACC(v0.y, 1)  ACC(v0.z, 2)  ACC(v0.w, 3)
        ACC(v1.x, 4)  ACC(v1.y, 5)  ACC(v1.z, 6)  ACC(v1.w, 7)
        ACC(v2.x, 8)  ACC(v2.y, 9)  ACC(v2.z,10)  ACC(v2.w,11)
        ACC(v3.x,12)  ACC(v3.y,13)  ACC(v3.z,14)  ACC(v3.w,15)
        #undef ACC

        // gelu(h)*wf == h' * (1 + erf(h')) * (0.5/KI)*wf,  h' = h/sqrt(2)
        float q0 = erf1p(h0);
        float q1 = erf1p(h1);
        float q2 = erf1p(h2);
        float q3 = erf1p(h3);
        float q4 = erf1p(h4);
        float acc = (h0 * wq[0]) * q0;
        acc = fmaf(h1 * wq[1], q1, acc);
        acc = fmaf(h2 * wq[2], q2, acc);
        acc = fmaf(h3 * wq[3], q3, acc);
        acc = fmaf(h4 * wq[4], q4, acc);

        s_out[warp * CPB + (p * 32 + lane)] = acc;
    }
    __syncthreads();

    // ---- transposed write: 16B per thread-cell; adjacent blockIdx.x
    //      supplies the neighboring half-sector -> L2 write-merge.
    #pragma unroll
    for (int cc = 0; cc < CPB; cc += 128) {
        const int c = cc + threadIdx.x;
        float4 o;
        o.x = s_out[0 * CPB + c];
        o.y = s_out[1 * CPB + c];
        o.z = s_out[2 * CPB + c];
        o.w = s_out[3 * CPB + c];
        float* op = out + (size_t)(c0 + c) * RR + (size_t)blockIdx.x * RPB;
        *(float4*)op = o;
    }
}

extern "C" void kernel_launch(void* const* d_in, const int* in_sizes, int n_in,
                              void* d_out, int out_size)
{
    const float* emb = (const float*)d_in[0];   // [R, C, DIN] f32
    const void*  oi  = d_in[1];                 // [R] int32/int64
    const float* W1  = (const float*)d_in[2];   // [NREG, DIN, E]
    const float* b1  = (const float*)d_in[3];   // [NREG, E]
    const float* Wf  = (const float*)d_in[4];   // [NREG, E, 1]
    float* out = (float*)d_out;                 // [C, R]

    dim3 grid(RR / RPB, CC / CPB);              // (256, 32) region-group fast
    e2e_kernel<<<grid, 128>>>(emb, oi, W1, b1, Wf, out);
}

// round 12
// speedup vs baseline: 1.0451x; 1.0217x over previous
#include <cuda_runtime.h>
#include <math.h>

// EmbeddingToExpression: per-region MLP 16 -> 5 (exact-erf GELU) -> 1
//   R=1024, C=8192, DIN=16, E=5, NREG=2048. out[c,r] f32.
//
// R12: weights move registers -> SMEM broadcast to unlock occupancy.
// R11 evidence: 16 warps/SM pins DRAM at 76% regardless of issue. The
// 80-float weight array was the register wall. Weights are warp-uniform
// => LDS broadcast (1 wavefront / 32 lanes). Each warp stages its 320 B
// of prescaled weights once, then 20x LDS.128 broadcast per pass.
// Regs ~64 -> __launch_bounds__(128,6): 24 warps/SM (occ 37.5%).
// cp.async DEPTH-3 ring (warp-private, no cross-warp sync), embedding
// bytes still read exactly once. SMEM ~30 KB/CTA -> 6 CTAs fit.

#define RR      1024
#define CC      8192
#define DIN     16
#define EE      5
#define CPB     256          // cells per block
#define RPB     4            // regions per block (one warp each)
#define PASSES  8            // CPB / 32
#define DEPTH   3            // pipeline ring depth
#define STAGE_B 2048         // 32 cells * 64 B per warp-pass
#define WPW     (DIN * EE)   // 80 weights per region

__device__ __forceinline__ unsigned sw128(unsigned o) {
    return o ^ ((o >> 3) & 0x70);
}
__device__ __forceinline__ void cp16(unsigned dst, const void* src) {
    asm volatile("cp.async.cg.shared.global [%0], [%1], 16;\n"
                 :: "r"(dst), "l"(src));
}
__device__ __forceinline__ void cp_commit() {
    asm volatile("cp.async.commit_group;\n" ::: "memory");
}
__device__ __forceinline__ void cp_wait2() {
    asm volatile("cp.async.wait_group 2;\n" ::: "memory");
}

// 1 + erf(x), branchless. Abramowitz-Stegun 7.1.25, |abs err| <= 2.5e-5.
__device__ __forceinline__ float erf1p(float x) {
    const float p  = 0.47047f;
    const float a1 = 0.3480242f, a2 = -0.0958798f, a3 = 0.7478556f;
    float ax = fabsf(x);
    float t  = __fdividef(1.0f, fmaf(p, ax, 1.0f));   // MUFU.RCP
    float r  = fmaf(a3, t, a2);
    r = fmaf(r, t, a1);
    r = r * t;
    float u = r * __expf(-x * x);                     // MUFU.EX2
    return 1.0f + copysignf(1.0f - u, x);
}

__global__ __launch_bounds__(128, 6)
void e2e_kernel(const float* __restrict__ emb,
                const void*  __restrict__ oi,     // int32 or int64, detected
                const float* __restrict__ W1,     // [NREG, DIN, E]
                const float* __restrict__ b1,     // [NREG, E]
                const float* __restrict__ Wf,     // [NREG, E, 1]
                float* __restrict__ out)          // [C, R]
{
    __shared__ __align__(1024) char s_stage[RPB * DEPTH * STAGE_B]; // 24 KB
    __shared__ float s_out[RPB * CPB];                              // 4 KB
    __shared__ __align__(16) float s_w[RPB * WPW];                  // 1.25 KB
    __shared__ int   s_is64;

    // Detect regions_oi width (values < 2048 => int64 high words are 0).
    if (threadIdx.x == 0) {
        const int* w = (const int*)oi;
        int all0 = 1;
        #pragma unroll
        for (int k = 0; k < 32; k++) all0 &= (w[2 * k + 1] == 0);
        s_is64 = all0;
    }
    __syncthreads();

    const int warp = threadIdx.x >> 5;
    const int lane = threadIdx.x & 31;
    const int r    = blockIdx.x * RPB + warp;   // region group = FAST grid dim
    const int c0   = blockIdx.y * CPB;

    int reg;
    if (s_is64) reg = (int)((const long long*)oi)[r];
    else        reg = ((const int*)oi)[r];

    // ---- hoisted swizzled offsets + pipeline bases ----
    const char* gsrc = (const char*)(emb + ((size_t)r * CC + c0) * DIN);
    char*       wbuf = s_stage + warp * (DEPTH * STAGE_B);
    const unsigned sbase = (unsigned)__cvta_generic_to_shared(wbuf);
    unsigned po[4], co[4];
    #pragma unroll
    for (int k = 0; k < 4; k++) {
        po[k] = sw128(k * 512 + lane * 16);     // producer dst offsets
        co[k] = sw128(lane * 64 + k * 16);      // consumer src offsets
    }
    const unsigned goff = lane * 16;

    // ---- start DRAM traffic first: prologue stages 0..1 ----
    #pragma unroll
    for (int g = 0; g < DEPTH - 1; g++) {
        const unsigned slot = sbase + g * STAGE_B;
        const char* s = gsrc + g * STAGE_B + goff;
        cp16(slot + po[0], s);
        cp16(slot + po[1], s + 512);
        cp16(slot + po[2], s + 1024);
        cp16(slot + po[3], s + 1536);
        cp_commit();
    }

    // ---- stage this warp's 80 weights (prescaled by 1/sqrt2) to SMEM ----
    const float KI = 0.70710678118654752f;      // 1/sqrt(2)
    const float KQ = 0.70710678118654752f;      // 0.5/KI
    {
        const float* wrow = W1 + (size_t)reg * WPW;
        float* wsm = s_w + warp * WPW;
        #pragma unroll
        for (int j = 0; j < 3; j++) {
            int idx = lane * 3 + j;             // 0..95 covers 0..79
            if (idx < WPW) wsm[idx] = wrow[idx] * KI;
        }
        __syncwarp();
    }
    float bb[EE], wq[EE];
    #pragma unroll
    for (int e = 0; e < EE; e++) {
        bb[e] = b1[reg * EE + e] * KI;
        wq[e] = Wf[reg * EE + e] * KQ;          // 0.5/KI * wf
    }
    const float4* w4 = (const float4*)(s_w + warp * WPW);   // 20 vec4

    #pragma unroll
    for (int p = 0; p < PASSES; p++) {
        const int g = p + DEPTH - 1;
        if (g < PASSES) {
            const unsigned slot = sbase + (g % DEPTH) * STAGE_B;
            const char* s = gsrc + g * STAGE_B + goff;
            cp16(slot + po[0], s);
            cp16(slot + po[1], s + 512);
            cp16(slot + po[2], s + 1024);
            cp16(slot + po[3], s + 1536);
        }
        cp_commit();
        cp_wait2();   // all but newest 2 groups done => stage p landed

        // ---- compute pass p: x from staged tile, weights via LDS
        //      broadcast (warp-uniform address => 1 wavefront) ----
        const char* xb = wbuf + (p % DEPTH) * STAGE_B;
        float4 v0 = *(const float4*)(xb + co[0]);
        float4 v1 = *(const float4*)(xb + co[1]);
        float4 v2 = *(const float4*)(xb + co[2]);
        float4 v3 = *(const float4*)(xb + co[3]);
        float x[DIN] = { v0.x, v0.y, v0.z, v0.w,
                         v1.x, v1.y, v1.z, v1.w,
                         v2.x, v2.y, v2.z, v2.w,
                         v3.x, v3.y, v3.z, v3.w };

        float h0 = bb[0], h1 = bb[1], h2 = bb[2], h3 = bb[3], h4 = bb[4];
        #pragma unroll
        for (int q = 0; q < WPW / 4; q++) {     // 20 LDS.128 broadcasts
            float4 wv = w4[q];
            // flat f = 4q+j: x index f/5, h index f%5 (all compile-time)
            #define F(J, WV) {                                   \
                constexpr int f = 0;                             \
                (void)f;                                         \
            }
            #undef F
            {
                const int f0 = 4 * q + 0, f1 = 4 * q + 1;
                const int f2 = 4 * q + 2, f3 = 4 * q + 3;
                float* hp[5] = { &h0, &h1, &h2, &h3, &h4 };
                *hp[f0 % 5] = fmaf(x[f0 / 5], wv.x, *hp[f0 % 5]);
                *hp[f1 % 5] = fmaf(x[f1 / 5], wv.y, *hp[f1 % 5]);
                *hp[f2 % 5] = fmaf(x[f2 / 5], wv.z, *hp[f2 % 5]);
                *hp[f3 % 5] = fmaf(x[f3 / 5], wv.w, *hp[f3 % 5]);
            }
        }

        // gelu(h)*wf == h' * (1 + erf(h')) * (0.5/KI)*wf,  h' = h/sqrt(2)
        float q0 = erf1p(h0);
        float q1 = erf1p(h1);
        float q2 = erf1p(h2);
        float q3 = erf1p(h3);
        float q4 = erf1p(h4);
        float acc = (h0 * wq[0]) * q0;
        acc = fmaf(h1 * wq[1], q1, acc);
        acc = fmaf(h2 * wq[2], q2, acc);
        acc = fmaf(h3 * wq[3], q3, acc);
        acc = fmaf(h4 * wq[4], q4, acc);

        s_out[warp * CPB + (p * 32 + lane)] = acc;
    }
    __syncthreads();

    // ---- transposed write: 16B per thread-cell; adjacent blockIdx.x
    //      supplies the neighboring half-sector -> L2 write-merge.
    #pragma unroll
    for (int cc = 0; cc < CPB; cc += 128) {
        const int c = cc + threadIdx.x;
        float4 o;
        o.x = s_out[0 * CPB + c];
        o.y = s_out[1 * CPB + c];
        o.z = s_out[2 * CPB + c];
        o.w = s_out[3 * CPB + c];
        float* op = out + (size_t)(c0 + c) * RR + (size_t)blockIdx.x * RPB;
        *(float4*)op = o;
    }
}

extern "C" void kernel_launch(void* const* d_in, const int* in_sizes, int n_in,
                              void* d_out, int out_size)
{
    const float* emb = (const float*)d_in[0];   // [R, C, DIN] f32
    const void*  oi  = d_in[1];                 // [R] int32/int64
    const float* W1  = (const float*)d_in[2];   // [NREG, DIN, E]
    const float* b1  = (const float*)d_in[3];   // [NREG, E]
    const float* Wf  = (const float*)d_in[4];   // [NREG, E, 1]
    float* out = (float*)d_out;                 // [C, R]

    dim3 grid(RR / RPB, CC / CPB);              // (256, 32) region-group fast
    e2e_kernel<<<grid, 128>>>(emb, oi, W1, b1, Wf, out);
}